// round 9
// baseline (speedup 1.0000x reference)
#include <cuda_runtime.h>
#include <math.h>

#define HC_F 1.9864458571489287e-25f

#define M_MAX    65536
#define N_MAX    8192
#define M_CHUNKS 128
#define NT       256
#define RPT      4           // rays per thread; column width = NT*RPT = 1024
#define NBX_MAX  8           // max ray columns (n <= 8192)

typedef unsigned long long u64;

__device__ __align__(16) float g_sx[M_MAX/2 + 640];  // SoA unit vectors, zero-padded
__device__ __align__(16) float g_sy[M_MAX/2 + 640];
__device__ __align__(16) float g_sz[M_MAX/2 + 640];
__device__ unsigned g_final[N_MAX];       // order-encoded max |dot| per ray (self-resetting)
__device__ int      g_colcnt[NBX_MAX];    // per-column completion counters (self-resetting)
__device__ float    g_psum[NBX_MAX];      // per-column partial sums
__device__ int      g_done = 0;           // final ticket (self-resetting)

// order-preserving float<->uint encoding (monotonic, exact); values here >= 0
__device__ __forceinline__ unsigned enc_f(float f) {
    unsigned u = __float_as_uint(f);
    return (u & 0x80000000u) ? ~u : (u | 0x80000000u);
}
__device__ __forceinline__ float dec_f(unsigned k) {
    return __uint_as_float((k & 0x80000000u) ? (k ^ 0x80000000u) : ~k);
}

// packed f32x2 helpers (sm_100+)
__device__ __forceinline__ u64 pack2(float lo, float hi) {
    u64 r; asm("mov.b64 %0, {%1, %2};" : "=l"(r) : "f"(lo), "f"(hi)); return r;
}
__device__ __forceinline__ u64 mul2(u64 a, u64 b) {
    u64 d; asm("mul.rn.f32x2 %0, %1, %2;" : "=l"(d) : "l"(a), "l"(b)); return d;
}
__device__ __forceinline__ u64 fma2(u64 a, u64 b, u64 c) {
    u64 d; asm("fma.rn.f32x2 %0, %1, %2, %3;" : "=l"(d) : "l"(a), "l"(b), "l"(c)); return d;
}
__device__ __forceinline__ void maxabs2(float& mv, u64 t) {
    float lo, hi;
    asm("mov.b64 {%0, %1}, %2;" : "=f"(lo), "=f"(hi) : "l"(t));
    mv = fmaxf(mv, fabsf(lo));   // FMNMX absorbs the abs
    mv = fmaxf(mv, fabsf(hi));
}

// ---------------------------------------------------------------------------
// k1: transform the lex-positive half [m/2, m) of the symmetric hkl list into
// global SoA unit vectors; zero-pad [half, pad_total) so every k2 chunk scans
// a uniform quad-aligned span. hkl[i] = -hkl[m-1-i]; u(-hkl) = -u(hkl) with
// identical energy, so max_i dot == max over the half of |dot|. Masked or
// padded entries are zero vectors (|dot| contribution 0; in the all-masked
// corner exp(-0.5(pi/2/pm)^2) == 0 == reference's exp at pi, exact).
// Every thread rebuilds RL = rot @ inv(prim)^T in registers via __sincosf
// (identical everywhere -> deterministic; trivially parallel).
// ---------------------------------------------------------------------------
__global__ void k1(const float* __restrict__ lattice, const float* __restrict__ angle,
                   const int* __restrict__ hkl, int m, int pad_total,
                   const float* __restrict__ e_min_p) {
    int half = m >> 1;
    int j = blockIdx.x * blockDim.x + threadIdx.x;
    if (j >= pad_total) return;
    if (j >= half) {                       // zero pad region
        g_sx[j] = 0.0f; g_sy[j] = 0.0f; g_sz[j] = 0.0f;
        return;
    }

    float a = lattice[0], b = lattice[1], c = lattice[2];
    float cal, sal, cbe, sbe, cga, sga;
    __sincosf(lattice[3], &sal, &cal);
    __sincosf(lattice[4], &sbe, &cbe);
    __sincosf(lattice[5], &sga, &cga);
    float e3y = (cal - cbe * cga) / sga;
    float e3z = sqrtf(fmaxf(1.0f - cbe * cbe - e3y * e3y, 1e-12f));

    float P00 = a, P01 = b*cga, P02 = c*cbe;
    float          P11 = b*sga, P12 = c*e3y;
    float                       P22 = c*e3z;
    // upper-triangular inverse, R = inv(P)^T (lower-triangular)
    float i00 = 1.0f / P00, i11 = 1.0f / P11, i22 = 1.0f / P22;
    float i01 = -P01 * i00 * i11;
    float i12 = -P12 * i11 * i22;
    float i02 = (P01 * P12 - P02 * P11) * i00 * i11 * i22;
    float R00 = i00, R10 = i01, R20 = i02;
    float R11 = i11, R21 = i12;
    float R22 = i22;

    float c0, s0, c1, s1, c2, s2;
    __sincosf(angle[0], &s0, &c0);
    __sincosf(angle[1], &s1, &c1);
    __sincosf(angle[2], &s2, &c2);
    // rot = Rx(t0) @ Ry(t1) @ Rz(t2)
    float m00 = c1*c2,             m01 = -c1*s2,            m02 = s1;
    float m10 = s0*s1*c2 + c0*s2,  m11 = -s0*s1*s2 + c0*c2, m12 = -s0*c1;
    float m20 = -c0*s1*c2 + s0*s2, m21 = c0*s1*s2 + s0*c2,  m22 = c0*c1;
    // RL = rot @ R (R lower-triangular)
    float RL00 = m00*R00 + m01*R10 + m02*R20;
    float RL01 =           m01*R11 + m02*R21;
    float RL02 =                     m02*R22;
    float RL10 = m10*R00 + m11*R10 + m12*R20;
    float RL11 =           m11*R11 + m12*R21;
    float RL12 =                     m12*R22;
    float RL20 = m20*R00 + m21*R10 + m22*R20;
    float RL21 =           m21*R11 + m22*R21;
    float RL22 =                     m22*R22;

    int gi = half + j;
    float h = (float)hkl[3*gi+0];
    float k = (float)hkl[3*gi+1];
    float l = (float)hkl[3*gi+2];
    float qx = RL00*h + RL01*k + RL02*l;
    float qy = RL10*h + RL11*k + RL12*l;
    float qz = RL20*h + RL21*k + RL22*l;
    float qn = sqrtf(qx*qx + qy*qy + qz*qz);
    float rinv = 1.0f / qn;
    float ux = qx*rinv, uy = qy*rinv, uz = qz*rinv;
    float energy = HC_F * qn / (2.0f * fmaxf(fabsf(uz), 1e-9f));
    bool kept = (energy >= e_min_p[0]);

    g_sx[j] = kept ? ux : 0.0f;
    g_sy[j] = kept ? uy : 0.0f;
    g_sz[j] = kept ? uz : 0.0f;
}

// ---------------------------------------------------------------------------
// k2: grid (nbx, M_CHUNKS). No shared memory, no pre-mainloop barrier: each
// thread streams its uniform chunk4-element span via warp-uniform
// __ldg(ulonglong2) broadcasts (L1/L2-resident after k1), packed f32x2 dots
// for RPT rays tracking max |dot|, folded into g_final via order-encoded
// atomicMax (exact, order-independent -> deterministic). Column-last block
// computes the acos/exp partial for its 1024 rays (atomicExch read+reset);
// the final ticket block sums column partials in fixed order. All state
// self-resets for graph replay.
// ---------------------------------------------------------------------------
__global__ void __launch_bounds__(NT) k2(const float* __restrict__ uq_exp,
                                         int n, int chunk4,
                                         const float* __restrict__ phi_max_p,
                                         float* __restrict__ out) {
    // ray loads
    int ridx[RPT];
    u64 exb[RPT], eyb[RPT], ezb[RPT];
    #pragma unroll
    for (int r = 0; r < RPT; r++) {
        int gi = blockIdx.x * (NT * RPT) + r * NT + threadIdx.x;
        ridx[r] = gi;
        float ex = 0.0f, ey = 0.0f, ez = 0.0f;
        if (gi < n) {
            ex = uq_exp[3*gi+0];
            ey = uq_exp[3*gi+1];
            ez = uq_exp[3*gi+2];
        }
        exb[r] = pack2(ex, ex);
        eyb[r] = pack2(ey, ey);
        ezb[r] = pack2(ez, ez);
    }

    int start = blockIdx.y * chunk4;       // 4-aligned by construction
    const ulonglong2* px = (const ulonglong2*)(g_sx + start);
    const ulonglong2* py = (const ulonglong2*)(g_sy + start);
    const ulonglong2* pz = (const ulonglong2*)(g_sz + start);
    int quads = chunk4 >> 2;

    float mv[RPT];
    #pragma unroll
    for (int r = 0; r < RPT; r++) mv[r] = 0.0f;   // |dot| >= 0

    #pragma unroll 2
    for (int q = 0; q < quads; q++) {
        ulonglong2 X = __ldg(&px[q]);
        ulonglong2 Y = __ldg(&py[q]);
        ulonglong2 Z = __ldg(&pz[q]);
        #pragma unroll
        for (int r = 0; r < RPT; r++) {
            u64 t0 = mul2(X.x, exb[r]);
            t0 = fma2(Y.x, eyb[r], t0);
            t0 = fma2(Z.x, ezb[r], t0);
            u64 t1 = mul2(X.y, exb[r]);
            t1 = fma2(Y.y, eyb[r], t1);
            t1 = fma2(Z.y, ezb[r], t1);
            maxabs2(mv[r], t0);
            maxabs2(mv[r], t1);
        }
    }

    #pragma unroll
    for (int r = 0; r < RPT; r++)
        if (ridx[r] < n) atomicMax(&g_final[ridx[r]], enc_f(mv[r]));

    // ---- column-last detection ----
    __threadfence();
    __shared__ int s_collast;
    if (threadIdx.x == 0) {
        int t = atomicAdd(&g_colcnt[blockIdx.x], 1);
        s_collast = (t == (int)gridDim.y - 1) ? 1 : 0;
    }
    __syncthreads();
    if (!s_collast) return;

    // ---- per-column epilogue: acos/exp partial over this column's rays ----
    float pm = phi_max_p[0];
    int rbase = blockIdx.x * (NT * RPT);
    int rcount = n - rbase;
    if (rcount > NT * RPT) rcount = NT * RPT;

    float sum = 0.0f;
    for (int i = threadIdx.x; i < rcount; i += NT) {
        unsigned kbits = atomicExch(&g_final[rbase + i], 0u);  // read + reset
        float mc = dec_f(kbits);
        mc = fminf(mc, 1.0f - 1e-6f);        // mc >= 0, only upper clip binds
        float phi = acosf(mc);
        float t = phi / pm;
        sum += expf(-0.5f * t * t);
    }

    __shared__ float red[NT];
    red[threadIdx.x] = sum;
    __syncthreads();
    for (int off = NT/2; off > 0; off >>= 1) {
        if (threadIdx.x < off) red[threadIdx.x] += red[threadIdx.x + off];
        __syncthreads();
    }

    if (threadIdx.x == 0) {
        g_psum[blockIdx.x] = red[0];
        g_colcnt[blockIdx.x] = 0;            // reset column counter for replay
        __threadfence();
        int t = atomicAdd(&g_done, 1);
        if (t == (int)gridDim.x - 1) {
            __threadfence();
            float tot = 0.0f;
            for (int b = 0; b < (int)gridDim.x; b++)   // fixed order -> deterministic
                tot += ((volatile float*)g_psum)[b];
            out[0] = tot / (float)n;
            g_done = 0;                      // reset ticket for replay
        }
    }
}

// ---------------------------------------------------------------------------
extern "C" void kernel_launch(void* const* d_in, const int* in_sizes, int n_in,
                              void* d_out, int out_size) {
    const float* lattice = (const float*)d_in[0];
    const float* angle   = (const float*)d_in[1];
    const float* uq_exp  = (const float*)d_in[2];
    const int*   hkl     = (const int*)d_in[3];
    const float* phi_max = (const float*)d_in[4];
    const float* e_min   = (const float*)d_in[5];

    int n = in_sizes[2] / 3;
    int m = in_sizes[3] / 3;
    if (m > M_MAX) m = M_MAX;
    if (n > N_MAX) n = N_MAX;

    int half = m >> 1;
    int chunk4 = (((half + M_CHUNKS - 1) / M_CHUNKS) + 3) & ~3;  // quad-aligned chunk
    int pad_total = chunk4 * M_CHUNKS;                           // <= half + 4*M_CHUNKS

    k1<<<(pad_total + 255) / 256, 256>>>(lattice, angle, hkl, m, pad_total, e_min);

    int nbx = (n + NT * RPT - 1) / (NT * RPT);
    if (nbx > NBX_MAX) nbx = NBX_MAX;
    dim3 g2(nbx, M_CHUNKS);
    k2<<<g2, NT>>>(uq_exp, n, chunk4, phi_max, (float*)d_out);
}

// round 10
// speedup vs baseline: 1.2731x; 1.2731x over previous
#include <cuda_runtime.h>
#include <math.h>

#define HC_F 1.9864458571489287e-25f

#define M_MAX    65536
#define N_MAX    8192
#define NCH      148         // chunk count == SM count; grid = (nbx, NCH)
#define NT       256
#define RPT      4           // rays per thread; column width = NT*RPT = 1024
#define NBX_MAX  8           // max ray columns (n <= 8192)
#define TILE     232         // >= max chunk4 (ceil(32768/148)+3 = 225) + pad

typedef unsigned long long u64;

__device__ unsigned g_final[N_MAX];       // order-encoded max |dot| per ray (self-resetting)
__device__ int      g_colcnt[NBX_MAX];    // per-column completion counters (self-resetting)
__device__ float    g_psum[NBX_MAX];      // per-column partial sums
__device__ int      g_done = 0;           // final ticket (self-resetting)

// order-preserving float<->uint encoding (monotonic, exact); values here >= 0
__device__ __forceinline__ unsigned enc_f(float f) {
    unsigned u = __float_as_uint(f);
    return (u & 0x80000000u) ? ~u : (u | 0x80000000u);
}
__device__ __forceinline__ float dec_f(unsigned k) {
    return __uint_as_float((k & 0x80000000u) ? (k ^ 0x80000000u) : ~k);
}

// packed f32x2 helpers (sm_100+)
__device__ __forceinline__ u64 pack2(float lo, float hi) {
    u64 r; asm("mov.b64 %0, {%1, %2};" : "=l"(r) : "f"(lo), "f"(hi)); return r;
}
__device__ __forceinline__ u64 mul2(u64 a, u64 b) {
    u64 d; asm("mul.rn.f32x2 %0, %1, %2;" : "=l"(d) : "l"(a), "l"(b)); return d;
}
__device__ __forceinline__ u64 fma2(u64 a, u64 b, u64 c) {
    u64 d; asm("fma.rn.f32x2 %0, %1, %2, %3;" : "=l"(d) : "l"(a), "l"(b), "l"(c)); return d;
}
__device__ __forceinline__ void maxabs2(float& mv, u64 t) {
    float lo, hi;
    asm("mov.b64 {%0, %1}, %2;" : "=f"(lo), "=f"(hi) : "l"(t));
    mv = fmaxf(mv, fabsf(lo));   // FMNMX absorbs the abs
    mv = fmaxf(mv, fabsf(hi));
}

// ---------------------------------------------------------------------------
// Fully fused single kernel. Grid (nbx, NCH), NT threads. 5*148 = 740 blocks
// = exactly 5 resident CTAs per SM at 48 regs (no partial wave).
//
// Symmetry: hkl[i] = -hkl[m-1-i]; u(-hkl) = -u(hkl) with identical energy, so
// max_i dot(e, u_i) == max over the lex-positive half [m/2, m) of |dot|.
// Energy-masked entries become zero vectors (|dot| contribution 0; in the
// all-masked corner exp(-0.5(pi/2/pm)^2) == 0 == reference's exp at pi).
//
// Per block: each transform-owning thread (<= 1 element each, chunk4 <= 256)
// issues its hkl loads FIRST, then rebuilds RL = rot@inv(prim)^T in registers
// with __sincosf while the loads are in flight (identical everywhere ->
// deterministic), and writes its element to the smem SoA tile. Mainloop:
// ulonglong2 4-element shared loads, packed f32x2 dots for RPT rays/thread,
// max |dot| folded into g_final via order-encoded atomicMax (exact,
// order-independent). Column-last block computes the acos/exp partial for its
// 1024 rays (atomicExch read+reset); final ticket block sums column partials
// in fixed order. All state self-resets for graph replay.
// ---------------------------------------------------------------------------
__global__ void __launch_bounds__(NT) k2(const float* __restrict__ lattice,
                                         const float* __restrict__ angle,
                                         const int*   __restrict__ hkl,
                                         const float* __restrict__ uq_exp,
                                         int n, int m, int chunk4,
                                         const float* __restrict__ phi_max_p,
                                         const float* __restrict__ e_min_p,
                                         float* __restrict__ out) {
    __shared__ __align__(16) float sx[TILE];
    __shared__ __align__(16) float sy[TILE];
    __shared__ __align__(16) float sz[TILE];

    // ---- ray loads first (long latency, overlap everything) ----
    int ridx[RPT];
    float exs[RPT], eys[RPT], ezs[RPT];
    #pragma unroll
    for (int r = 0; r < RPT; r++) {
        int gi = blockIdx.x * (NT * RPT) + r * NT + threadIdx.x;
        ridx[r] = gi;
        if (gi < n) {
            exs[r] = uq_exp[3*gi+0];
            eys[r] = uq_exp[3*gi+1];
            ezs[r] = uq_exp[3*gi+2];
        } else {
            exs[r] = 0.0f; eys[r] = 0.0f; ezs[r] = 0.0f;
        }
    }

    int half = m >> 1;
    int start = blockIdx.y * chunk4;
    int len = half - start;
    if (len > chunk4) len = chunk4;
    if (len < 0) len = 0;

    // ---- transform: <=1 element/thread; hkl loads issued before trig ----
    if (threadIdx.x < len) {
        int gi = half + start + threadIdx.x;
        float h = (float)hkl[3*gi+0];        // LDGs in flight during trig below
        float k = (float)hkl[3*gi+1];
        float l = (float)hkl[3*gi+2];
        float emin = e_min_p[0];

        float a = lattice[0], b = lattice[1], c = lattice[2];
        float cal, sal, cbe, sbe, cga, sga;
        __sincosf(lattice[3], &sal, &cal);
        __sincosf(lattice[4], &sbe, &cbe);
        __sincosf(lattice[5], &sga, &cga);
        float e3y = (cal - cbe * cga) / sga;
        float e3z = sqrtf(fmaxf(1.0f - cbe * cbe - e3y * e3y, 1e-12f));

        float P00 = a, P01 = b*cga, P02 = c*cbe;
        float          P11 = b*sga, P12 = c*e3y;
        float                       P22 = c*e3z;
        // upper-triangular inverse; R = inv(P)^T (lower-triangular)
        float i00 = 1.0f / P00, i11 = 1.0f / P11, i22 = 1.0f / P22;
        float i01 = -P01 * i00 * i11;
        float i12 = -P12 * i11 * i22;
        float i02 = (P01 * P12 - P02 * P11) * i00 * i11 * i22;
        float R00 = i00, R10 = i01, R20 = i02;
        float R11 = i11, R21 = i12;
        float R22 = i22;

        float c0, s0, c1, s1, c2, s2;
        __sincosf(angle[0], &s0, &c0);
        __sincosf(angle[1], &s1, &c1);
        __sincosf(angle[2], &s2, &c2);
        // rot = Rx(t0) @ Ry(t1) @ Rz(t2)
        float m00 = c1*c2,             m01 = -c1*s2,            m02 = s1;
        float m10 = s0*s1*c2 + c0*s2,  m11 = -s0*s1*s2 + c0*c2, m12 = -s0*c1;
        float m20 = -c0*s1*c2 + s0*s2, m21 = c0*s1*s2 + s0*c2,  m22 = c0*c1;
        // RL = rot @ R (R lower-triangular)
        float RL00 = m00*R00 + m01*R10 + m02*R20;
        float RL01 =           m01*R11 + m02*R21;
        float RL02 =                     m02*R22;
        float RL10 = m10*R00 + m11*R10 + m12*R20;
        float RL11 =           m11*R11 + m12*R21;
        float RL12 =                     m12*R22;
        float RL20 = m20*R00 + m21*R10 + m22*R20;
        float RL21 =           m21*R11 + m22*R21;
        float RL22 =                     m22*R22;

        float qx = RL00*h + RL01*k + RL02*l;
        float qy = RL10*h + RL11*k + RL12*l;
        float qz = RL20*h + RL21*k + RL22*l;
        float qn = sqrtf(qx*qx + qy*qy + qz*qz);
        float rinv = 1.0f / qn;
        float ux = qx*rinv, uy = qy*rinv, uz = qz*rinv;
        float energy = HC_F * qn / (2.0f * fmaxf(fabsf(uz), 1e-9f));
        bool kept = (energy >= emin);
        sx[threadIdx.x] = kept ? ux : 0.0f;
        sy[threadIdx.x] = kept ? uy : 0.0f;
        sz[threadIdx.x] = kept ? uz : 0.0f;
    } else if (threadIdx.x < chunk4) {       // zero-pad [len, chunk4)
        sx[threadIdx.x] = 0.0f;
        sy[threadIdx.x] = 0.0f;
        sz[threadIdx.x] = 0.0f;
    }

    // packed ray broadcasts
    u64 exb[RPT], eyb[RPT], ezb[RPT];
    #pragma unroll
    for (int r = 0; r < RPT; r++) {
        exb[r] = pack2(exs[r], exs[r]);
        eyb[r] = pack2(eys[r], eys[r]);
        ezb[r] = pack2(ezs[r], ezs[r]);
    }

    __syncthreads();

    float mv[RPT];
    #pragma unroll
    for (int r = 0; r < RPT; r++) mv[r] = 0.0f;   // |dot| >= 0

    const ulonglong2* qx2 = (const ulonglong2*)sx;
    const ulonglong2* qy2 = (const ulonglong2*)sy;
    const ulonglong2* qz2 = (const ulonglong2*)sz;
    int quads = chunk4 >> 2;

    #pragma unroll 2
    for (int q = 0; q < quads; q++) {
        ulonglong2 X = qx2[q];
        ulonglong2 Y = qy2[q];
        ulonglong2 Z = qz2[q];
        #pragma unroll
        for (int r = 0; r < RPT; r++) {
            u64 t0 = mul2(X.x, exb[r]);
            t0 = fma2(Y.x, eyb[r], t0);
            t0 = fma2(Z.x, ezb[r], t0);
            u64 t1 = mul2(X.y, exb[r]);
            t1 = fma2(Y.y, eyb[r], t1);
            t1 = fma2(Z.y, ezb[r], t1);
            maxabs2(mv[r], t0);
            maxabs2(mv[r], t1);
        }
    }

    #pragma unroll
    for (int r = 0; r < RPT; r++)
        if (ridx[r] < n) atomicMax(&g_final[ridx[r]], enc_f(mv[r]));

    // ---- column-last detection ----
    __threadfence();
    __shared__ int s_collast;
    if (threadIdx.x == 0) {
        int t = atomicAdd(&g_colcnt[blockIdx.x], 1);
        s_collast = (t == (int)gridDim.y - 1) ? 1 : 0;
    }
    __syncthreads();
    if (!s_collast) return;

    // ---- per-column epilogue: acos/exp partial over this column's rays ----
    float pm = phi_max_p[0];
    int rbase = blockIdx.x * (NT * RPT);
    int rcount = n - rbase;
    if (rcount > NT * RPT) rcount = NT * RPT;

    float sum = 0.0f;
    for (int i = threadIdx.x; i < rcount; i += NT) {
        unsigned kbits = atomicExch(&g_final[rbase + i], 0u);  // read + reset
        float mc = dec_f(kbits);
        mc = fminf(mc, 1.0f - 1e-6f);        // mc >= 0, only upper clip binds
        float phi = acosf(mc);
        float t = phi / pm;
        sum += expf(-0.5f * t * t);
    }

    __shared__ float red[NT];
    red[threadIdx.x] = sum;
    __syncthreads();
    for (int off = NT/2; off > 0; off >>= 1) {
        if (threadIdx.x < off) red[threadIdx.x] += red[threadIdx.x + off];
        __syncthreads();
    }

    if (threadIdx.x == 0) {
        g_psum[blockIdx.x] = red[0];
        g_colcnt[blockIdx.x] = 0;            // reset column counter for replay
        __threadfence();
        int t = atomicAdd(&g_done, 1);
        if (t == (int)gridDim.x - 1) {
            __threadfence();
            float tot = 0.0f;
            for (int b = 0; b < (int)gridDim.x; b++)   // fixed order -> deterministic
                tot += ((volatile float*)g_psum)[b];
            out[0] = tot / (float)n;
            g_done = 0;                      // reset ticket for replay
        }
    }
}

// ---------------------------------------------------------------------------
extern "C" void kernel_launch(void* const* d_in, const int* in_sizes, int n_in,
                              void* d_out, int out_size) {
    const float* lattice = (const float*)d_in[0];
    const float* angle   = (const float*)d_in[1];
    const float* uq_exp  = (const float*)d_in[2];
    const int*   hkl     = (const int*)d_in[3];
    const float* phi_max = (const float*)d_in[4];
    const float* e_min   = (const float*)d_in[5];

    int n = in_sizes[2] / 3;
    int m = in_sizes[3] / 3;
    if (m > M_MAX) m = M_MAX;
    if (n > N_MAX) n = N_MAX;

    int half = m >> 1;
    int chunk4 = (((half + NCH - 1) / NCH) + 3) & ~3;   // quad-aligned chunk
    if (chunk4 > NT) chunk4 = NT;                        // transform: 1 elem/thread max
    // ensure coverage if clamped (only possible for m near M_MAX)
    while (chunk4 * NCH < half) chunk4 += 4;             // still <= TILE for m <= M_MAX

    int nbx = (n + NT * RPT - 1) / (NT * RPT);
    if (nbx > NBX_MAX) nbx = NBX_MAX;
    dim3 g2(nbx, NCH);
    k2<<<g2, NT>>>(lattice, angle, hkl, uq_exp, n, m, chunk4, phi_max, e_min, (float*)d_out);
}